// round 2
// baseline (speedup 1.0000x reference)
#include <cuda_runtime.h>
#include <cuda_bf16.h>
#include <math.h>

#define BTOT   16384
#define LSTEPS 64
#define NBR    8
#define HD     128
#define RB     32
#define NTHR   256
#define BLQ    (BTOT*LSTEPS)

// ---------------- device scratch (allocation-free workaround) ----------------
__device__ float g_wihp[128*512];        // w_ih packed: [k][v], v = j*4+q, gate g=q*128+j
__device__ float g_wpack[129*512];       // w_hh packed: [k][v]  (+1 pad row for prefetch)
__device__ float g_rowIH[8*512];         // 0.5 * (w_emb @ w_ih^T), packed [branch][v]
__device__ float g_bsum[512];            // (b_ih + b_hh) packed [v]
__device__ float g_cIH[1000*512];        // g_emb @ w_ih^T, packed [class][v]
__device__ float g_base[BTOT*512];       // per-row: 0.5*classIH + bsum, packed [row][v]

// ---------------- packed f32x2 helpers ----------------
__device__ __forceinline__ unsigned long long dup2(float x){
    unsigned long long r;
    asm("mov.b64 %0, {%1, %1};" : "=l"(r) : "f"(x));
    return r;
}
__device__ __forceinline__ unsigned long long pack2(float lo, float hi){
    unsigned long long r;
    asm("mov.b64 %0, {%1, %2};" : "=l"(r) : "f"(lo), "f"(hi));
    return r;
}
__device__ __forceinline__ float2 unpack2(unsigned long long v){
    float2 f;
    asm("mov.b64 {%0, %1}, %2;" : "=f"(f.x), "=f"(f.y) : "l"(v));
    return f;
}
__device__ __forceinline__ void fma2(unsigned long long &d, unsigned long long a, unsigned long long b){
    asm("fma.rn.f32x2 %0, %1, %2, %0;" : "+l"(d) : "l"(a), "l"(b));
}
__device__ __forceinline__ float sigf(float x){ return 1.0f/(1.0f + expf(-x)); }

// ---------------- prep kernels ----------------
__global__ void prep_wihp(const float* __restrict__ w_ih){
    int idx = blockIdx.x*blockDim.x + threadIdx.x;   // 65536
    int k = idx >> 9, v = idx & 511;
    int jj = v >> 2, q = v & 3;
    g_wihp[idx] = w_ih[(q*128 + jj)*128 + k];
}

__global__ void prep_misc(const float* __restrict__ w_hh, const float* __restrict__ b_ih,
                          const float* __restrict__ b_hh, const float* __restrict__ w_emb){
    int idx = blockIdx.x*blockDim.x + threadIdx.x;   // 65536
    int k = idx >> 9, v = idx & 511;
    int jj = v >> 2, q = v & 3;
    g_wpack[idx] = w_hh[(q*128 + jj)*128 + k];
    if (idx < 512){
        int jj2 = idx >> 2, q2 = idx & 3;
        g_bsum[idx] = b_ih[q2*128 + jj2] + b_hh[q2*128 + jj2];
    }
    if (idx < 8*512){
        int b = idx >> 9, vv = idx & 511;
        float s = 0.f;
        for (int kk = 0; kk < 128; kk++)
            s = fmaf(w_emb[b*128 + kk], g_wihp[kk*512 + vv], s);
        g_rowIH[idx] = 0.5f * s;
    }
}

__global__ void prep_cIH(const float* __restrict__ g_emb){
    __shared__ float ge[8][128];
    int c0 = blockIdx.x * 8;                          // 125 blocks x 512 threads
    for (int i = threadIdx.x; i < 8*128; i += 512)
        ge[i >> 7][i & 127] = g_emb[c0*128 + i];
    __syncthreads();
    int v = threadIdx.x;
    float s[8];
    #pragma unroll
    for (int cc = 0; cc < 8; cc++) s[cc] = 0.f;
    for (int k = 0; k < 128; k++){
        float w = g_wihp[k*512 + v];
        #pragma unroll
        for (int cc = 0; cc < 8; cc++) s[cc] = fmaf(ge[cc][k], w, s[cc]);
    }
    #pragma unroll
    for (int cc = 0; cc < 8; cc++) g_cIH[(size_t)(c0+cc)*512 + v] = s[cc];
}

__global__ void prep_base(const int* __restrict__ cls){
    size_t idx = (size_t)blockIdx.x*blockDim.x + threadIdx.x;  // 8.39M
    int r = (int)(idx >> 9), v = (int)(idx & 511);
    g_base[idx] = 0.5f * g_cIH[(size_t)__ldg(cls + r)*512 + v] + g_bsum[v];
}

// ---------------- main persistent controller kernel ----------------
__global__ void __launch_bounds__(NTHR, 2)
ctrl_main(const float* __restrict__ gumbel, const float* __restrict__ w_soft,
          float* __restrict__ out)
{
    extern __shared__ float sm[];
    float* hbuf0 = sm;                    // [128][68]
    float* hbuf1 = sm + 8704;             // [128][68]
    float* ws    = sm + 17408;            // [8][132] padded w_soft
    int*   brs   = (int*)(sm + 17408 + 1056);  // [32] branches

    const int t   = threadIdx.x;
    const int rg  = t >> 7;               // 0..1  (row-group)
    const int j   = t & 127;              // hidden unit
    const int row0 = blockIdx.x * RB;
    const int lr0 = rg * 16;              // local row base for this thread
    const int grow = row0 + lr0;          // global row base

    for (int i = t; i < 8*128; i += NTHR)
        ws[(i >> 7)*132 + (i & 127)] = w_soft[i];

    float c[16];
    #pragma unroll
    for (int i = 0; i < 16; i++) c[i] = 0.f;

    const float4* Wp4   = (const float4*)g_wpack;
    const float4* base4 = (const float4*)g_base;
    const float4* rih4  = (const float4*)g_rowIH;
    const float4* bs4   = (const float4*)g_bsum;

    float* cur = hbuf1;
    float* nxt = hbuf0;

    const int rl = t >> 3;                // 0..31 row for sampling phase
    const int nb = t & 7;                 // branch lane

    for (int step = 0; step < LSTEPS; step++){
        unsigned long long acc[8][4];

        if (step == 0){
            // gates = classIH + bsum = 2*base - bsum ; h=0 so no GEMM
            float4 s4 = __ldg(bs4 + j);
            #pragma unroll
            for (int p = 0; p < 8; p++){
                float4 b0 = __ldg(base4 + (size_t)(grow + 2*p    )*128 + j);
                float4 b1 = __ldg(base4 + (size_t)(grow + 2*p + 1)*128 + j);
                acc[p][0] = pack2(2.f*b0.x - s4.x, 2.f*b1.x - s4.x);
                acc[p][1] = pack2(2.f*b0.y - s4.y, 2.f*b1.y - s4.y);
                acc[p][2] = pack2(2.f*b0.z - s4.z, 2.f*b1.z - s4.z);
                acc[p][3] = pack2(2.f*b0.w - s4.w, 2.f*b1.w - s4.w);
            }
        } else {
            // gates init = base + 0.5*rowIH[branch]
            #pragma unroll
            for (int p = 0; p < 8; p++){
                int br0 = brs[lr0 + 2*p], br1 = brs[lr0 + 2*p + 1];
                float4 b0 = __ldg(base4 + (size_t)(grow + 2*p    )*128 + j);
                float4 b1 = __ldg(base4 + (size_t)(grow + 2*p + 1)*128 + j);
                float4 e0 = __ldg(rih4 + br0*128 + j);
                float4 e1 = __ldg(rih4 + br1*128 + j);
                acc[p][0] = pack2(b0.x + e0.x, b1.x + e1.x);
                acc[p][1] = pack2(b0.y + e0.y, b1.y + e1.y);
                acc[p][2] = pack2(b0.z + e0.z, b1.z + e1.z);
                acc[p][3] = pack2(b0.w + e0.w, b1.w + e1.w);
            }
            // GEMM: acc += h @ W_hh^T   (f32x2 packed over row pairs)
            const ulonglong2* hsu = (const ulonglong2*)cur;
            float4 wv = __ldg(Wp4 + j);
            #pragma unroll 4
            for (int k = 0; k < 128; k++){
                float4 wc = wv;
                wv = __ldg(Wp4 + (k+1)*128 + j);       // pad row 128 exists
                unsigned long long w0 = dup2(wc.x), w1 = dup2(wc.y),
                                   w2 = dup2(wc.z), w3 = dup2(wc.w);
                #pragma unroll
                for (int u = 0; u < 4; u++){
                    ulonglong2 hp = hsu[k*17 + rg*4 + u];
                    fma2(acc[2*u  ][0], hp.x, w0); fma2(acc[2*u  ][1], hp.x, w1);
                    fma2(acc[2*u  ][2], hp.x, w2); fma2(acc[2*u  ][3], hp.x, w3);
                    fma2(acc[2*u+1][0], hp.y, w0); fma2(acc[2*u+1][1], hp.y, w1);
                    fma2(acc[2*u+1][2], hp.y, w2); fma2(acc[2*u+1][3], hp.y, w3);
                }
            }
        }

        // ---- LSTM cell (c in regs), write h2 into 'nxt' transposed [j][row] ----
        #pragma unroll
        for (int p = 0; p < 8; p++){
            float2 gi = unpack2(acc[p][0]);
            float2 gf = unpack2(acc[p][1]);
            float2 gg = unpack2(acc[p][2]);
            float2 go = unpack2(acc[p][3]);
            {
                int i = 2*p;
                float cn = sigf(gf.x)*c[i] + sigf(gi.x)*tanhf(gg.x);
                float hn = sigf(go.x)*tanhf(cn);
                c[i] = cn;
                nxt[j*68 + lr0 + i] = hn;
            }
            {
                int i = 2*p + 1;
                float cn = sigf(gf.y)*c[i] + sigf(gi.y)*tanhf(gg.y);
                float hn = sigf(go.y)*tanhf(cn);
                c[i] = cn;
                nxt[j*68 + lr0 + i] = hn;
            }
        }
        __syncthreads();

        // ---- logit + gumbel-max sample: thread (rl, nb) ----
        {
            const float* hcol = nxt + rl;
            const float* wr   = ws + nb*132;
            float s0 = 0.f, s1 = 0.f;
            #pragma unroll
            for (int k = 0; k < 128; k += 2){
                s0 = fmaf(hcol[k*68],      wr[k],   s0);
                s1 = fmaf(hcol[(k+1)*68],  wr[k+1], s1);
            }
            float lraw = s0 + s1;
            float lgt  = 2.5f * tanhf(lraw / 5.0f);

            float u  = __ldg(gumbel + ((size_t)step*BTOT + row0 + rl)*8 + nb);
            float uc = fminf(fmaxf(u, 1e-8f), 1.0f - 1e-8f);
            float gmb = -logf(-logf(uc));
            float y = lgt + gmb;

            int   ibest = nb;
            float ybest = y;
            #pragma unroll
            for (int d = 1; d < 8; d <<= 1){
                float oy = __shfl_xor_sync(0xffffffffu, ybest, d);
                int   oi = __shfl_xor_sync(0xffffffffu, ibest, d);
                if (oy > ybest || (oy == ybest && oi < ibest)){ ybest = oy; ibest = oi; }
            }

            float m = lgt;
            #pragma unroll
            for (int d = 1; d < 8; d <<= 1)
                m = fmaxf(m, __shfl_xor_sync(0xffffffffu, m, d));
            float e = expf(lgt - m);
            float ssum = e;
            #pragma unroll
            for (int d = 1; d < 8; d <<= 1)
                ssum += __shfl_xor_sync(0xffffffffu, ssum, d);
            float lp = lgt - m - logf(ssum);
            float pe = expf(lp);
            float et = pe * lp;
            float ent = et;
            #pragma unroll
            for (int d = 1; d < 8; d <<= 1)
                ent += __shfl_xor_sync(0xffffffffu, ent, d);
            ent = -ent;

            if (nb == ibest){
                size_t oidx = (size_t)(row0 + rl)*LSTEPS + step;
                out[oidx]           = (float)ibest;   // sample_arc
                out[BLQ   + oidx]   = lp;             // sample_log_prob
                out[2*BLQ + oidx]   = ent;            // sample_entropy
                out[3*BLQ + oidx]   = pe;             // sample_prob
                brs[rl] = ibest;
            }
        }
        __syncthreads();

        float* tmp = cur; cur = nxt; nxt = tmp;
    }
}

// ---------------- launch ----------------
extern "C" void kernel_launch(void* const* d_in, const int* in_sizes, int n_in,
                              void* d_out, int out_size)
{
    const int*   cls   = (const int*)  d_in[0];
    const float* gum   = (const float*)d_in[1];
    const float* gemb  = (const float*)d_in[2];
    const float* wemb  = (const float*)d_in[3];
    const float* wsoft = (const float*)d_in[4];
    const float* wih   = (const float*)d_in[5];
    const float* whh   = (const float*)d_in[6];
    const float* bih   = (const float*)d_in[7];
    const float* bhh   = (const float*)d_in[8];
    float* out = (float*)d_out;

    const size_t smem = (size_t)(17408 + 1056 + 32) * sizeof(float);  // 73,984 B
    cudaFuncSetAttribute(ctrl_main, cudaFuncAttributeMaxDynamicSharedMemorySize, (int)smem);

    prep_wihp<<<256, 256>>>(wih);
    prep_misc<<<256, 256>>>(whh, bih, bhh, wemb);
    prep_cIH<<<125, 512>>>(gemb);
    prep_base<<<32768, 256>>>(cls);
    ctrl_main<<<512, NTHR, smem>>>(gum, wsoft, out);
}